// round 16
// baseline (speedup 1.0000x reference)
#include <cuda_runtime.h>
#include <cooperative_groups.h>

namespace cg = cooperative_groups;

#define EPS 1e-8f
typedef unsigned long long ull;

// Shapes: b=4, m=8, n=128, d=64
__device__ float g_hgw[4 * 8 * 64];     // hg * |w|
__device__ float g_hfw[4 * 128 * 64];   // (hf + b1) * |w|
__device__ float g_htw[4 * 128 * 64];   // ht * |w|
__device__ float g_linG[4 * 8];         // sum_e hg*w
__device__ float g_linF[4 * 128];       // sum_e (hf+b1)*w
__device__ float g_linT[4 * 128];       // sum_e ht*w
__device__ float g_buf[4 * 8 * 128 * 128];
__device__ float g_rowpart[4 * 8 * 128];
__device__ unsigned g_tick;             // monotonic ticket barrier (never reset)

#define K1_BLOCKS 528u

__device__ __forceinline__ void pdl_trigger() {
    asm volatile("griddepcontrol.launch_dependents;" ::: "memory");
}
__device__ __forceinline__ void pdl_wait() {
    asm volatile("griddepcontrol.wait;" ::: "memory");
}

__device__ __forceinline__ float warpReduceSum(float v) {
#pragma unroll
    for (int o = 16; o; o >>= 1) v += __shfl_xor_sync(0xffffffffu, v, o);
    return v;
}

// ---- packed f32x2 helpers ----
__device__ __forceinline__ ull pk2(float x, float y) {
    ull r;
    asm("mov.b64 %0, {%1, %2};" : "=l"(r) : "f"(x), "f"(y));
    return r;
}
__device__ __forceinline__ float lo2(ull a) {
    float x;
    asm("{ .reg .b32 hi; mov.b64 {%0, hi}, %1; }" : "=f"(x) : "l"(a));
    return x;
}
__device__ __forceinline__ float hi2(ull a) {
    float x;
    asm("{ .reg .b32 lo; mov.b64 {lo, %0}, %1; }" : "=f"(x) : "l"(a));
    return x;
}
__device__ __forceinline__ ull mul2(ull a, ull b) {
    ull d;
    asm("mul.rn.f32x2 %0, %1, %2;" : "=l"(d) : "l"(a), "l"(b));
    return d;
}
__device__ __forceinline__ ull add2(ull a, ull b) {
    ull d;
    asm("add.rn.f32x2 %0, %1, %2;" : "=l"(d) : "l"(a), "l"(b));
    return d;
}

// acc2 += sign2 .* |gw2 + th2|
__device__ __forceinline__ void mac2(ull& acc, ull gw, ull th, unsigned sl, unsigned sh2) {
    asm("{\n\t"
        ".reg .b64 h2, t2;\n\t"
        ".reg .b32 lo, hi;\n\t"
        "add.rn.f32x2 h2, %1, %2;\n\t"
        "mov.b64 {lo, hi}, h2;\n\t"
        "lop3.b32 lo, lo, 0x7fffffff, %3, 0x6A;\n\t"
        "lop3.b32 hi, hi, 0x7fffffff, %4, 0x6A;\n\t"
        "mov.b64 t2, {lo, hi};\n\t"
        "add.rn.f32x2 %0, %0, t2;\n\t"
        "}"
        : "+l"(acc)
        : "l"(gw), "l"(th), "r"(sl), "r"(sh2));
}

// ---------------------------------------------------------------------------
// K1: FUSED projections + scores. Grid (132,4) x 128.
// Phase A: block handles 2 projection rows (blk*2, blk*2+1); segment layout
//   8 (hg) | 128 (hf) | 128 (ht) — even boundaries, no 2-row block straddles.
// Ticket barrier (monotonic counter, replay-safe): all 528 blocks arrive;
//   only blocks with f = blockIdx.x < 128 wait and run Phase B.
// Phase B: R13 k_out body (no max subtraction — cancels in layer-0 norm).
// All 528 blocks are co-resident in wave 1 (capacity >= 2368), so the spin
// cannot deadlock.
// ---------------------------------------------------------------------------
__global__ void __launch_bounds__(128) k1(const float* __restrict__ cities,
                                          const float* __restrict__ groups,
                                          const float* __restrict__ W1,
                                          const float* __restrict__ b1,
                                          const float* __restrict__ W2,
                                          const float* __restrict__ b2) {
    pdl_trigger();
    const int b = blockIdx.y, blk = blockIdx.x, t = threadIdx.x;
    const int half = t >> 6, e = t & 63;
    const int w = t >> 5, lane = t & 31;

    __shared__ float xv[2][64];
    __shared__ float sred2[2][2];
    __shared__ __align__(16) ull sh_gw[8 * 32];
    __shared__ __align__(16) unsigned sh_sgu[64];
    __shared__ float sh_linG[8];
    __shared__ float s_red[8][4];

    // ================= Phase A: projection of 2 rows =================
    {
        int r = blk * 2 + half;
        const float* x;
        float* outw;
        float* lin;
        int woff;
        float badd = 0.f;
        if (r < 8) {
            x = groups + (b * 8 + r) * 64;
            outw = g_hgw + (b * 8 + r) * 64;
            lin = g_linG + b * 8 + r;
            woff = 0;
        } else if (r < 136) {
            int f = r - 8;
            x = cities + (b * 128 + f) * 64;
            outw = g_hfw + (b * 128 + f) * 64;
            lin = g_linF + b * 128 + f;
            woff = 64;
            badd = b1[e];
        } else {
            int tt = r - 136;
            x = cities + (b * 128 + tt) * 64;
            outw = g_htw + (b * 128 + tt) * 64;
            lin = g_linT + b * 128 + tt;
            woff = 128;
        }
        xv[half][e] = x[e];
        __syncthreads();

        const float* Wbase = W1 + woff * 64 + e;
        float acc = 0.f;
#pragma unroll
        for (int kb = 0; kb < 64; kb += 16) {
            float wv[16];
#pragma unroll
            for (int i = 0; i < 16; i++) wv[i] = Wbase[(kb + i) * 64];
#pragma unroll
            for (int i = 0; i < 16; i++) acc += xv[half][kb + i] * wv[i];
        }
        float h = acc + badd;
        float ww = W2[e];
        outw[e] = h * fabsf(ww);

        float p = warpReduceSum(h * ww);
        if (lane == 0) sred2[half][(e >> 5)] = p;
        __syncthreads();
        if (e == 0) *lin = sred2[half][0] + sred2[half][1];
    }

    // ================= ticket barrier (replay-safe) =================
    const bool is_scorer = (blk < 128);
    __syncthreads();
    if (t == 0) {
        __threadfence();
        unsigned r = atomicAdd(&g_tick, 1u);
        if (is_scorer) {
            unsigned target = (r / K1_BLOCKS + 1u) * K1_BLOCKS;
            unsigned v;
            do {
                asm volatile("ld.global.acquire.gpu.u32 %0, [%1];"
                             : "=r"(v) : "l"(&g_tick));
                if ((int)(v - target) >= 0) break;
                __nanosleep(64);
            } while (true);
        }
    }
    if (!is_scorer) return;  // blocks 128..131: arrive-only
    __syncthreads();

    // ================= Phase B: scoring (R13 k_out body) =================
    const int f = blk;
    if (t < 64) sh_sgu[t] = __float_as_uint(W2[t]) & 0x80000000u;
    float b2v = b2[0];

    for (int idx = t; idx < 256; idx += 128) {
        int m = idx >> 5, ee2 = idx & 31;
        int ee = 2 * ee2;
        float a0 = g_hgw[(b * 8 + m) * 64 + ee] + g_hfw[(b * 128 + f) * 64 + ee];
        float a1 = g_hgw[(b * 8 + m) * 64 + ee + 1] + g_hfw[(b * 128 + f) * 64 + ee + 1];
        sh_gw[m * 32 + ee2] = (ull)__float_as_uint(a0) | ((ull)__float_as_uint(a1) << 32);
    }
    if (t < 8) sh_linG[t] = g_linG[b * 8 + t];
    __syncthreads();

    union {
        float4 f4[16];
        ull u[32];
    } tw;
    const float4* src = (const float4*)(g_htw + (b * 128 + t) * 64);
#pragma unroll
    for (int i = 0; i < 16; i++) tw.f4[i] = src[i];

    ull accs[8];
#pragma unroll
    for (int m = 0; m < 8; m++) accs[m] = 0ull;
#pragma unroll
    for (int ee2 = 0; ee2 < 32; ee2++) {
        unsigned sl = sh_sgu[2 * ee2], sh2 = sh_sgu[2 * ee2 + 1];
        ull th = tw.u[ee2];
#pragma unroll
        for (int m = 0; m < 8; m++) mac2(accs[m], sh_gw[m * 32 + ee2], th, sl, sh2);
    }

    float linFT = g_linF[b * 128 + f] + g_linT[b * 128 + t];
#pragma unroll
    for (int m = 0; m < 8; m++) {
        float nl = __uint_as_float((unsigned)(accs[m] & 0xffffffffull)) +
                   __uint_as_float((unsigned)(accs[m] >> 32));
        float val = 0.5f * (sh_linG[m] + linFT + nl) + b2v;
        float ev = expf(val);  // no max subtraction (cancels in normalization)
        g_buf[((b * 8 + m) * 128 + f) * 128 + t] = ev;
        float s = warpReduceSum(ev);
        if (lane == 0) s_red[m][w] = s;
    }
    __syncthreads();
    if (t < 8)
        g_rowpart[(b * 8 + t) * 128 + f] =
            (s_red[t][0] + s_red[t][1]) + (s_red[t][2] + s_red[t][3]);
}

// ---------------------------------------------------------------------------
// K2 k_soft: R14 verbatim (best config — cluster.sync gather, split tail bar).
// ---------------------------------------------------------------------------
__global__ void __cluster_dims__(8, 1, 1) __launch_bounds__(1024, 1)
k_soft(float* __restrict__ out) {
    cg::cluster_group cl = cg::this_cluster();
    const int rk = (int)cl.block_rank();
    const int b = blockIdx.x >> 3;
    const int tid = threadIdx.x;
    const int x = tid >> 3;
    const int jq = tid & 7;
    const int w = tid >> 5;
    const int lane = tid & 31;
    const int yb = rk * 16;
    const bool x0 = (x == 0);
    const bool y0th = (rk == 0 && jq == 0);

    __shared__ __align__(16) float s_dinv[128];
    __shared__ __align__(16) float s_d0inv[8];
    __shared__ __align__(16) float s_cdinv[16];
    __shared__ __align__(16) float s_c0inv[8];
    __shared__ __align__(16) float s_wpp[32][16];
    __shared__ __align__(16) float s_y0p[32][8];
    __shared__ __align__(16) float s_xs[2][128];
    __shared__ __align__(16) float s_x0[2][8];

    pdl_wait();

    // ---- load slab packed ----
    ull V[8];
#pragma unroll
    for (int m = 0; m < 8; m++) {
        const float2* p =
            (const float2*)(g_buf + ((size_t)((b * 8 + m) * 128 + x)) * 128 + yb + jq * 2);
        float2 t2 = *p;
        V[m] = pk2(t2.x, t2.y);
    }

    // ---- layer-0 even dens from g_rowpart ----
    if (tid < 128) {
        float d = 0.f;
#pragma unroll
        for (int m = 0; m < 8; m++) d += g_rowpart[(b * 8 + m) * 128 + tid];
        s_dinv[tid] = 1.0f / d;
    } else if (tid < 136) {
        s_d0inv[tid - 128] = 1.0f / g_rowpart[(b * 8 + (tid - 128)) * 128];
    }
    __syncthreads();

#pragma unroll 1
    for (int half = 0; half < 5; half++) {
        // ===== EVEN layer scale (packed) + odd-den partials =====
        {
            float rinv = s_dinv[x];
            ull acc2 = 0ull;
#pragma unroll
            for (int m = 0; m < 8; m++) {
                float dm = x0 ? s_d0inv[m] : rinv;
                V[m] = mul2(V[m], pk2(dm, dm));
                acc2 = add2(acc2, V[m]);
            }
            float sj0 = lo2(acc2), sj1 = hi2(acc2);
            sj0 += __shfl_xor_sync(0xffffffffu, sj0, 8);
            sj0 += __shfl_xor_sync(0xffffffffu, sj0, 16);
            sj1 += __shfl_xor_sync(0xffffffffu, sj1, 8);
            sj1 += __shfl_xor_sync(0xffffffffu, sj1, 16);
            if ((lane >> 3) == 0) {
                s_wpp[w][jq * 2 + 0] = sj0;
                s_wpp[w][jq * 2 + 1] = sj1;
            }
            if (rk == 0) {
#pragma unroll
                for (int m = 0; m < 8; m++) {
                    float t = lo2(V[m]);
                    t += __shfl_xor_sync(0xffffffffu, t, 8);
                    t += __shfl_xor_sync(0xffffffffu, t, 16);
                    if (lane == 0) s_y0p[w][m] = t;
                }
            }
        }
        __syncthreads();  // bar1
        if (tid < 16) {
            float d = 0.f;
#pragma unroll
            for (int ww = 0; ww < 32; ww++) d += s_wpp[ww][tid];
            s_cdinv[tid] = 1.0f / d;
        } else if (tid < 24 && rk == 0) {
            int m = tid - 16;
            float d = 0.f;
#pragma unroll
            for (int ww = 0; ww < 32; ww++) d += s_y0p[ww][m];
            s_c0inv[m] = 1.0f / d;
        }
        __syncthreads();  // bar2

        // ===== ODD layer scale (packed) =====
        ull rj2 = *(const ull*)&s_cdinv[jq * 2];
        if (half == 4) {
#pragma unroll
            for (int m = 0; m < 8; m++) {
                ull s = y0th ? pk2(lo2(V[m]) * s_c0inv[m], hi2(V[m]) * hi2(rj2))
                             : mul2(V[m], rj2);
                float2 o;
                o.x = lo2(s);
                o.y = hi2(s);
                *(float2*)(out + ((size_t)((b * 8 + m) * 128 + x)) * 128 + yb + jq * 2) = o;
            }
            break;
        }
        {
            ull acc2 = 0ull;
#pragma unroll
            for (int m = 0; m < 8; m++) {
                ull s = y0th ? pk2(lo2(V[m]) * s_c0inv[m], hi2(V[m]) * hi2(rj2))
                             : mul2(V[m], rj2);
                V[m] = s;
                acc2 = add2(acc2, s);
            }
            float rp = lo2(acc2) + hi2(acc2);
            rp += __shfl_xor_sync(0xffffffffu, rp, 1);
            rp += __shfl_xor_sync(0xffffffffu, rp, 2);
            rp += __shfl_xor_sync(0xffffffffu, rp, 4);
            int p = half & 1;
            if ((lane & 7) == 0) s_xs[p][x] = rp;
            if (w == 0) {
#pragma unroll
                for (int m = 0; m < 8; m++) {
                    float t = lo2(V[m]) + hi2(V[m]);
                    t += __shfl_xor_sync(0xffffffffu, t, 1);
                    t += __shfl_xor_sync(0xffffffffu, t, 2);
                    t += __shfl_xor_sync(0xffffffffu, t, 4);
                    if (lane == 0) s_x0[p][m] = t;
                }
            }
        }
        cl.sync();

        // ---- gather peers' sums -> next even dens ----
        {
            int p = half & 1;
            if (tid < 128) {
                float d = 0.f;
#pragma unroll
                for (int r = 0; r < 8; r++) {
                    const float* pp = cl.map_shared_rank((const float*)&s_xs[p][0], r);
                    d += pp[tid];
                }
                s_dinv[tid] = 1.0f / d;
            } else if (tid < 136) {
                int m = tid - 128;
                float d = 0.f;
#pragma unroll
                for (int r = 0; r < 8; r++) {
                    const float* pp = cl.map_shared_rank((const float*)&s_x0[p][0], r);
                    d += pp[m];
                }
                s_d0inv[m] = 1.0f / d;
            }
        }
        __syncthreads();  // bar3

        if (half == 3) {
            asm volatile("barrier.cluster.arrive.aligned;" ::: "memory");
        }
    }

    asm volatile("barrier.cluster.wait.aligned;" ::: "memory");  // instant pass
}

// ---------------------------------------------------------------------------
// Launch: 2 kernels, PDL-chained.
// ---------------------------------------------------------------------------
extern "C" void kernel_launch(void* const* d_in, const int* in_sizes, int n_in,
                              void* d_out, int out_size) {
    const float* cities = (const float*)d_in[0];
    const float* groups = (const float*)d_in[1];
    const float* W1 = (const float*)d_in[2];
    const float* b1 = (const float*)d_in[3];
    const float* W2 = (const float*)d_in[4];
    const float* b2 = (const float*)d_in[5];
    float* out = (float*)d_out;

    k1<<<dim3(132, 4), 128>>>(cities, groups, W1, b1, W2, b2);

    {
        cudaLaunchConfig_t cfg = {};
        cfg.gridDim = dim3(32);
        cfg.blockDim = dim3(1024);
        cfg.stream = 0;
        cudaLaunchAttribute at[1];
        at[0].id = cudaLaunchAttributeProgrammaticStreamSerialization;
        at[0].val.programmaticStreamSerializationAllowed = 1;
        cfg.attrs = at;
        cfg.numAttrs = 1;
        cudaLaunchKernelEx(&cfg, k_soft, out);
    }
}

// round 17
// speedup vs baseline: 1.0691x; 1.0691x over previous
#include <cuda_runtime.h>
#include <cooperative_groups.h>

namespace cg = cooperative_groups;

#define EPS 1e-8f
typedef unsigned long long ull;

// Shapes: b=4, m=8, n=128, d=64
__device__ float g_hgw[4 * 8 * 64];     // hg * |w|
__device__ float g_hfw[4 * 128 * 64];   // (hf + b1) * |w|
__device__ float g_htw[4 * 128 * 64];   // ht * |w|
__device__ float g_linG[4 * 8];         // sum_e hg*w
__device__ float g_linF[4 * 128];       // sum_e (hf+b1)*w
__device__ float g_linT[4 * 128];       // sum_e ht*w
__device__ float g_buf[4 * 8 * 128 * 128];
__device__ float g_rowpart[4 * 8 * 128];

__device__ __forceinline__ void pdl_trigger() {
    asm volatile("griddepcontrol.launch_dependents;" ::: "memory");
}
__device__ __forceinline__ void pdl_wait() {
    asm volatile("griddepcontrol.wait;" ::: "memory");
}

__device__ __forceinline__ float warpReduceSum(float v) {
#pragma unroll
    for (int o = 16; o; o >>= 1) v += __shfl_xor_sync(0xffffffffu, v, o);
    return v;
}

// ---- packed f32x2 helpers ----
__device__ __forceinline__ ull pk2(float x, float y) {
    ull r;
    asm("mov.b64 %0, {%1, %2};" : "=l"(r) : "f"(x), "f"(y));
    return r;
}
__device__ __forceinline__ float lo2(ull a) {
    float x;
    asm("{ .reg .b32 hi; mov.b64 {%0, hi}, %1; }" : "=f"(x) : "l"(a));
    return x;
}
__device__ __forceinline__ float hi2(ull a) {
    float x;
    asm("{ .reg .b32 lo; mov.b64 {lo, %0}, %1; }" : "=f"(x) : "l"(a));
    return x;
}
__device__ __forceinline__ ull mul2(ull a, ull b) {
    ull d;
    asm("mul.rn.f32x2 %0, %1, %2;" : "=l"(d) : "l"(a), "l"(b));
    return d;
}
__device__ __forceinline__ ull add2(ull a, ull b) {
    ull d;
    asm("add.rn.f32x2 %0, %1, %2;" : "=l"(d) : "l"(a), "l"(b));
    return d;
}

// acc2 += sign2 .* |gw2 + th2|
__device__ __forceinline__ void mac2(ull& acc, ull gw, ull th, unsigned sl, unsigned sh2) {
    asm("{\n\t"
        ".reg .b64 h2, t2;\n\t"
        ".reg .b32 lo, hi;\n\t"
        "add.rn.f32x2 h2, %1, %2;\n\t"
        "mov.b64 {lo, hi}, h2;\n\t"
        "lop3.b32 lo, lo, 0x7fffffff, %3, 0x6A;\n\t"
        "lop3.b32 hi, hi, 0x7fffffff, %4, 0x6A;\n\t"
        "mov.b64 t2, {lo, hi};\n\t"
        "add.rn.f32x2 %0, %0, t2;\n\t"
        "}"
        : "+l"(acc)
        : "l"(gw), "l"(th), "r"(sl), "r"(sh2));
}

// ---------------------------------------------------------------------------
// K1 k_proj: grid (264,4), block 64 (R14 verbatim).
// ---------------------------------------------------------------------------
__global__ void __launch_bounds__(64) k_proj(const float* __restrict__ cities,
                                             const float* __restrict__ groups,
                                             const float* __restrict__ W1,
                                             const float* __restrict__ b1,
                                             const float* __restrict__ W2) {
    pdl_trigger();
    int b = blockIdx.y;
    int r = blockIdx.x;
    int e = threadIdx.x;
    __shared__ float xv[64];
    __shared__ float sred2[2];

    const float* x;
    float* outw;
    float* lin;
    int woff;
    float badd = 0.f;
    if (r < 8) {
        x = groups + (b * 8 + r) * 64;
        outw = g_hgw + (b * 8 + r) * 64;
        lin = g_linG + b * 8 + r;
        woff = 0;
    } else if (r < 136) {
        int f = r - 8;
        x = cities + (b * 128 + f) * 64;
        outw = g_hfw + (b * 128 + f) * 64;
        lin = g_linF + b * 128 + f;
        woff = 64;
        badd = b1[e];
    } else {
        int t = r - 136;
        x = cities + (b * 128 + t) * 64;
        outw = g_htw + (b * 128 + t) * 64;
        lin = g_linT + b * 128 + t;
        woff = 128;
    }
    xv[e] = x[e];
    __syncthreads();

    const float* Wbase = W1 + woff * 64 + e;
    float wv[64];
#pragma unroll
    for (int k = 0; k < 64; k++) wv[k] = Wbase[k * 64];
    float acc = 0.f;
#pragma unroll
    for (int k = 0; k < 64; k++) acc += xv[k] * wv[k];

    float h = acc + badd;
    float w = W2[e];
    outw[e] = h * fabsf(w);

    float p = warpReduceSum(h * w);
    if ((e & 31) == 0) sred2[e >> 5] = p;
    __syncthreads();
    if (e == 0) *lin = sred2[0] + sred2[1];
}

// ---------------------------------------------------------------------------
// K2 k_out v4 (R14 verbatim): grid (128,4) x 128, no max subtraction.
// ---------------------------------------------------------------------------
__global__ void __launch_bounds__(128) k_out(const float* __restrict__ W2,
                                             const float* __restrict__ b2) {
    pdl_trigger();
    int b = blockIdx.y, f = blockIdx.x, t = threadIdx.x;
    int w = t >> 5, lane = t & 31;
    __shared__ __align__(16) ull sh_gw[8 * 32];
    __shared__ __align__(16) unsigned sh_sgu[64];
    __shared__ float sh_linG[8];
    __shared__ float s_red[8][4];

    if (t < 64) sh_sgu[t] = __float_as_uint(W2[t]) & 0x80000000u;
    float b2v = b2[0];

    pdl_wait();

    for (int idx = t; idx < 256; idx += 128) {
        int m = idx >> 5, ee2 = idx & 31;
        int e = 2 * ee2;
        float a0 = g_hgw[(b * 8 + m) * 64 + e] + g_hfw[(b * 128 + f) * 64 + e];
        float a1 = g_hgw[(b * 8 + m) * 64 + e + 1] + g_hfw[(b * 128 + f) * 64 + e + 1];
        sh_gw[m * 32 + ee2] = (ull)__float_as_uint(a0) | ((ull)__float_as_uint(a1) << 32);
    }
    if (t < 8) sh_linG[t] = g_linG[b * 8 + t];
    __syncthreads();

    union {
        float4 f4[16];
        ull u[32];
    } tw;
    const float4* src = (const float4*)(g_htw + (b * 128 + t) * 64);
#pragma unroll
    for (int i = 0; i < 16; i++) tw.f4[i] = src[i];

    ull accs[8];
#pragma unroll
    for (int m = 0; m < 8; m++) accs[m] = 0ull;
#pragma unroll
    for (int ee2 = 0; ee2 < 32; ee2++) {
        unsigned sl = sh_sgu[2 * ee2], sh2 = sh_sgu[2 * ee2 + 1];
        ull th = tw.u[ee2];
#pragma unroll
        for (int m = 0; m < 8; m++) mac2(accs[m], sh_gw[m * 32 + ee2], th, sl, sh2);
    }

    float linFT = g_linF[b * 128 + f] + g_linT[b * 128 + t];
#pragma unroll
    for (int m = 0; m < 8; m++) {
        float nl = __uint_as_float((unsigned)(accs[m] & 0xffffffffull)) +
                   __uint_as_float((unsigned)(accs[m] >> 32));
        float val = 0.5f * (sh_linG[m] + linFT + nl) + b2v;
        float ev = expf(val);  // no max subtraction (cancels in normalization)
        g_buf[((b * 8 + m) * 128 + f) * 128 + t] = ev;
        float s = warpReduceSum(ev);
        if (lane == 0) s_red[m][w] = s;
    }
    __syncthreads();
    if (t < 8)
        g_rowpart[(b * 8 + t) * 128 + f] =
            (s_red[t][0] + s_red[t][1]) + (s_red[t][2] + s_red[t][3]);
}

// ---------------------------------------------------------------------------
// K3 k_soft: R14 base with ONE change — transposed, padded partial layouts
// (s_wpp[16][36], s_y0p[8][36]) so the per-layer den reduces use 8x LDS.128
// per reducer thread instead of 32 serial scalar LDS. Pad 36 keeps rows
// 16B-aligned and caps bank conflicts at 2-way for both stores and reads.
// ---------------------------------------------------------------------------
__global__ void __cluster_dims__(8, 1, 1) __launch_bounds__(1024, 1)
k_soft(float* __restrict__ out) {
    cg::cluster_group cl = cg::this_cluster();
    const int rk = (int)cl.block_rank();
    const int b = blockIdx.x >> 3;
    const int tid = threadIdx.x;
    const int x = tid >> 3;
    const int jq = tid & 7;
    const int w = tid >> 5;
    const int lane = tid & 31;
    const int yb = rk * 16;
    const bool x0 = (x == 0);
    const bool y0th = (rk == 0 && jq == 0);

    __shared__ __align__(16) float s_dinv[128];
    __shared__ __align__(16) float s_d0inv[8];
    __shared__ __align__(16) float s_cdinv[16];
    __shared__ __align__(16) float s_c0inv[8];
    __shared__ __align__(16) float s_wpp[16][36];  // [jq2][warp] transposed+padded
    __shared__ __align__(16) float s_y0p[8][36];   // [m][warp]
    __shared__ __align__(16) float s_xs[2][128];
    __shared__ __align__(16) float s_x0[2][8];

    pdl_wait();

    // ---- load slab packed ----
    ull V[8];
#pragma unroll
    for (int m = 0; m < 8; m++) {
        const float2* p =
            (const float2*)(g_buf + ((size_t)((b * 8 + m) * 128 + x)) * 128 + yb + jq * 2);
        float2 t2 = *p;
        V[m] = pk2(t2.x, t2.y);
    }

    // ---- layer-0 even dens from g_rowpart ----
    if (tid < 128) {
        float d = 0.f;
#pragma unroll
        for (int m = 0; m < 8; m++) d += g_rowpart[(b * 8 + m) * 128 + tid];
        s_dinv[tid] = 1.0f / d;
    } else if (tid < 136) {
        s_d0inv[tid - 128] = 1.0f / g_rowpart[(b * 8 + (tid - 128)) * 128];
    }
    __syncthreads();

#pragma unroll 1
    for (int half = 0; half < 5; half++) {
        // ===== EVEN layer scale (packed) + odd-den partials =====
        {
            float rinv = s_dinv[x];
            ull acc2 = 0ull;
#pragma unroll
            for (int m = 0; m < 8; m++) {
                float dm = x0 ? s_d0inv[m] : rinv;
                V[m] = mul2(V[m], pk2(dm, dm));
                acc2 = add2(acc2, V[m]);
            }
            float sj0 = lo2(acc2), sj1 = hi2(acc2);
            sj0 += __shfl_xor_sync(0xffffffffu, sj0, 8);
            sj0 += __shfl_xor_sync(0xffffffffu, sj0, 16);
            sj1 += __shfl_xor_sync(0xffffffffu, sj1, 8);
            sj1 += __shfl_xor_sync(0xffffffffu, sj1, 16);
            if ((lane >> 3) == 0) {  // lane == jq
                s_wpp[jq * 2 + 0][w] = sj0;
                s_wpp[jq * 2 + 1][w] = sj1;
            }
            if (rk == 0) {
#pragma unroll
                for (int m = 0; m < 8; m++) {
                    float t = lo2(V[m]);
                    t += __shfl_xor_sync(0xffffffffu, t, 8);
                    t += __shfl_xor_sync(0xffffffffu, t, 16);
                    if (lane == 0) s_y0p[m][w] = t;
                }
            }
        }
        __syncthreads();  // bar1
        if (tid < 16) {
            const float4* row = (const float4*)&s_wpp[tid][0];
            float d = 0.f;
#pragma unroll
            for (int q = 0; q < 8; q++) {
                float4 r4 = row[q];
                d += (r4.x + r4.y) + (r4.z + r4.w);
            }
            s_cdinv[tid] = 1.0f / d;
        } else if (tid < 24 && rk == 0) {
            const float4* row = (const float4*)&s_y0p[tid - 16][0];
            float d = 0.f;
#pragma unroll
            for (int q = 0; q < 8; q++) {
                float4 r4 = row[q];
                d += (r4.x + r4.y) + (r4.z + r4.w);
            }
            s_c0inv[tid - 16] = 1.0f / d;
        }
        __syncthreads();  // bar2

        // ===== ODD layer scale (packed) =====
        ull rj2 = *(const ull*)&s_cdinv[jq * 2];
        if (half == 4) {
#pragma unroll
            for (int m = 0; m < 8; m++) {
                ull s = y0th ? pk2(lo2(V[m]) * s_c0inv[m], hi2(V[m]) * hi2(rj2))
                             : mul2(V[m], rj2);
                float2 o;
                o.x = lo2(s);
                o.y = hi2(s);
                *(float2*)(out + ((size_t)((b * 8 + m) * 128 + x)) * 128 + yb + jq * 2) = o;
            }
            break;
        }
        {
            ull acc2 = 0ull;
#pragma unroll
            for (int m = 0; m < 8; m++) {
                ull s = y0th ? pk2(lo2(V[m]) * s_c0inv[m], hi2(V[m]) * hi2(rj2))
                             : mul2(V[m], rj2);
                V[m] = s;
                acc2 = add2(acc2, s);
            }
            float rp = lo2(acc2) + hi2(acc2);
            rp += __shfl_xor_sync(0xffffffffu, rp, 1);
            rp += __shfl_xor_sync(0xffffffffu, rp, 2);
            rp += __shfl_xor_sync(0xffffffffu, rp, 4);
            int p = half & 1;
            if ((lane & 7) == 0) s_xs[p][x] = rp;
            if (w == 0) {
#pragma unroll
                for (int m = 0; m < 8; m++) {
                    float t = lo2(V[m]) + hi2(V[m]);
                    t += __shfl_xor_sync(0xffffffffu, t, 1);
                    t += __shfl_xor_sync(0xffffffffu, t, 2);
                    t += __shfl_xor_sync(0xffffffffu, t, 4);
                    if (lane == 0) s_x0[p][m] = t;
                }
            }
        }
        cl.sync();

        // ---- gather peers' sums -> next even dens ----
        {
            int p = half & 1;
            if (tid < 128) {
                float d = 0.f;
#pragma unroll
                for (int r = 0; r < 8; r++) {
                    const float* pp = cl.map_shared_rank((const float*)&s_xs[p][0], r);
                    d += pp[tid];
                }
                s_dinv[tid] = 1.0f / d;
            } else if (tid < 136) {
                int m = tid - 128;
                float d = 0.f;
#pragma unroll
                for (int r = 0; r < 8; r++) {
                    const float* pp = cl.map_shared_rank((const float*)&s_x0[p][0], r);
                    d += pp[m];
                }
                s_d0inv[m] = 1.0f / d;
            }
        }
        __syncthreads();  // bar3

        if (half == 3) {
            asm volatile("barrier.cluster.arrive.aligned;" ::: "memory");
        }
    }

    asm volatile("barrier.cluster.wait.aligned;" ::: "memory");  // instant pass
}

// ---------------------------------------------------------------------------
// Launch: 3 kernels, PDL-chained (R14 verbatim).
// ---------------------------------------------------------------------------
extern "C" void kernel_launch(void* const* d_in, const int* in_sizes, int n_in,
                              void* d_out, int out_size) {
    const float* cities = (const float*)d_in[0];
    const float* groups = (const float*)d_in[1];
    const float* W1 = (const float*)d_in[2];
    const float* b1 = (const float*)d_in[3];
    const float* W2 = (const float*)d_in[4];
    const float* b2 = (const float*)d_in[5];
    float* out = (float*)d_out;

    k_proj<<<dim3(264, 4), 64>>>(cities, groups, W1, b1, W2);

    {
        cudaLaunchConfig_t cfg = {};
        cfg.gridDim = dim3(128, 4);
        cfg.blockDim = dim3(128);
        cfg.stream = 0;
        cudaLaunchAttribute at[1];
        at[0].id = cudaLaunchAttributeProgrammaticStreamSerialization;
        at[0].val.programmaticStreamSerializationAllowed = 1;
        cfg.attrs = at;
        cfg.numAttrs = 1;
        cudaLaunchKernelEx(&cfg, k_out, W2, b2);
    }

    {
        cudaLaunchConfig_t cfg = {};
        cfg.gridDim = dim3(32);
        cfg.blockDim = dim3(1024);
        cfg.stream = 0;
        cudaLaunchAttribute at[1];
        at[0].id = cudaLaunchAttributeProgrammaticStreamSerialization;
        at[0].val.programmaticStreamSerializationAllowed = 1;
        cfg.attrs = at;
        cfg.numAttrs = 1;
        cudaLaunchKernelEx(&cfg, k_soft, out);
    }
}